// round 6
// baseline (speedup 1.0000x reference)
#include <cuda_runtime.h>
#include <cstddef>

#define BB   512
#define SSC  1024
#define HHD  256
#define PIN  512
#define INDIM 19

#define MIMO_OFF (BB*SSC)              /* 524288 */
#define ATT_OFF  (MIMO_OFF + BB*8)     /* 528384 */
#define RAD_OFF  (ATT_OFF + BB*HHD)    /* 659456 */

// ---------------- device scratch (no allocations allowed) ----------------
__device__ __align__(256) float g_x[BB*INDIM];
__device__ __align__(256) float g_h0[2][BB*HHD];
__device__ __align__(256) float g_h1[2][BB*HHD];
__device__ __align__(256) float g_c[BB*2*HHD];

// ---------------- packed f32x2 helpers (Blackwell FFMA2) ----------------
__device__ __forceinline__ unsigned long long splat2(float a) {
    unsigned long long r;
    asm("mov.b64 %0, {%1, %1};" : "=l"(r) : "f"(a));
    return r;
}
__device__ __forceinline__ void ffma2(unsigned long long& d,
                                      unsigned long long a,
                                      unsigned long long b) {
    asm("fma.rn.f32x2 %0, %1, %2, %3;" : "=l"(d) : "l"(a), "l"(b), "l"(d));
}
__device__ __forceinline__ float2 unpack2(unsigned long long v) {
    float2 r;
    asm("mov.b64 {%0, %1}, %2;" : "=f"(r.x), "=f"(r.y) : "l"(v));
    return r;
}

// ---------------- concat x = [pos | ue | bs | extra] ----------------
__global__ void concat_kernel(const float* __restrict__ pos,
                              const float* __restrict__ ue,
                              const float* __restrict__ bsa,
                              const float* __restrict__ extra) {
    int b = threadIdx.x;
    if (b >= BB) return;
    float* x = g_x + b * INDIM;
    x[0] = pos[b*3+0]; x[1] = pos[b*3+1]; x[2] = pos[b*3+2];
    x[3] = ue[b*2+0];  x[4] = ue[b*2+1];
    x[5] = bsa[b*4+0]; x[6] = bsa[b*4+1]; x[7] = bsa[b*4+2]; x[8] = bsa[b*4+3];
    #pragma unroll
    for (int i = 0; i < 10; i++) x[9+i] = extra[b*10+i];
}

// ---------------- generic MLP layer: out = relu(A @ W^T + bias), both nets via blockIdx.z
struct MlpArgs {
    const float* A0; const float* A1;
    const float* W0; const float* W1;
    const float* bi0; const float* bi1;
    float* out0; float* out1;
    float* o20; float* o21;
    int lda, K, ostride, o2stride;
};

__global__ void __launch_bounds__(256) mlp_gemm_relu(MlpArgs p) {
    __shared__ __align__(16) float sA[16*66];
    __shared__ __align__(16) float sB[16*66];

    int net = blockIdx.z;
    const float* A    = net ? p.A1  : p.A0;
    const float* W    = net ? p.W1  : p.W0;
    const float* bias = net ? p.bi1 : p.bi0;
    float* out  = net ? p.out1 : p.out0;
    float* out2 = net ? p.o21  : p.o20;

    int b0 = blockIdx.x * 64, h0 = blockIdx.y * 64;
    int t  = threadIdx.x;
    int tx = t & 15, ty = t >> 4;     // 16 x 16 threads, 4x4 micro-tile
    int lr = t >> 2, lq = t & 3;      // load mapping: row 0..63, quarter 0..3

    unsigned long long acc[4][2];
    #pragma unroll
    for (int i = 0; i < 4; i++) { acc[i][0] = 0ull; acc[i][1] = 0ull; }

    int nkt = (p.K + 15) >> 4;
    for (int kt = 0; kt < nkt; ++kt) {
        int kbase = kt * 16;
        #pragma unroll
        for (int e = 0; e < 4; ++e) {
            int k = kbase + lq*4 + e;
            sA[(lq*4+e)*66 + lr] = (k < p.K) ? A[(size_t)(b0+lr)*p.lda + k] : 0.f;
            sB[(lq*4+e)*66 + lr] = (k < p.K) ? W[(size_t)(h0+lr)*p.K  + k] : 0.f;
        }
        __syncthreads();
        #pragma unroll
        for (int k = 0; k < 16; ++k) {
            unsigned long long bp0 = *(const unsigned long long*)&sB[k*66 + tx*4];
            unsigned long long bp1 = *(const unsigned long long*)&sB[k*66 + tx*4 + 2];
            #pragma unroll
            for (int i = 0; i < 4; ++i) {
                unsigned long long ap = splat2(sA[k*66 + ty*4 + i]);
                ffma2(acc[i][0], ap, bp0);
                ffma2(acc[i][1], ap, bp1);
            }
        }
        __syncthreads();
    }

    float bv[4];
    #pragma unroll
    for (int j = 0; j < 4; j++) bv[j] = bias[h0 + tx*4 + j];

    #pragma unroll
    for (int i = 0; i < 4; ++i) {
        int r = b0 + ty*4 + i;
        float2 v0 = unpack2(acc[i][0]);
        float2 v1 = unpack2(acc[i][1]);
        float o0 = fmaxf(v0.x + bv[0], 0.f);
        float o1 = fmaxf(v0.y + bv[1], 0.f);
        float o2 = fmaxf(v1.x + bv[2], 0.f);
        float o3 = fmaxf(v1.y + bv[3], 0.f);
        float* po = out + (size_t)r * p.ostride + h0 + tx*4;
        po[0] = o0; po[1] = o1; po[2] = o2; po[3] = o3;
        if (out2) {
            float* q = out2 + (size_t)r * p.o2stride + h0 + tx*4;
            q[0] = o0; q[1] = o1; q[2] = o2; q[3] = o3;
        }
    }
}

// ---------------- prism: per-subcarrier fused 3-layer MLP ----------------
// grid = (4 B-chunks, 1024 subcarriers), 512 threads, 1 CTA/SM (smem 173.6 KB)
__global__ void __launch_bounds__(512, 1) prism_kernel(
    const float* __restrict__ pw1, const float* __restrict__ pb1,
    const float* __restrict__ pw2, const float* __restrict__ pb2,
    const float* __restrict__ pw3, const float* __restrict__ pb3,
    float* __restrict__ out_sub)
{
    extern __shared__ float sm[];
    float* sA = sm;                         // [16][128]  C k-tiles (k-major)
    float* sB = sm + 16*128;                // [16][256]  W k-tiles (k-major)
    float* sH = sB + 16*256;                // [128][258] H1 (row-major, padded)
    float* sR = sH + 128*258;               // [128][33]  reduction scratch

    int s  = blockIdx.y;
    int b0 = blockIdx.x * 128;
    int t  = threadIdx.x;
    int tx = t & 31, ty = t >> 5;           // 32 x 16 threads, 8x8 micro-tile

    int ar = t & 127, aq = t >> 7;          // A-load: row, k-quarter (0..3)
    int bh = t & 255, bq = t >> 8;          // B-load: h,   k-half    (0..1)

    const float* w1s  = pw1 + (size_t)s * (HHD * PIN);
    const float* Crow = g_c + (size_t)(b0 + ar) * (2*HHD);

    unsigned long long acc[8][4];
    #pragma unroll
    for (int i = 0; i < 8; i++)
        #pragma unroll
        for (int j = 0; j < 4; j++) acc[i][j] = 0ull;

    // ---- Layer 1: H1[128,256] = relu(C[128,512] @ W1s^T + b1) ----
    for (int kt = 0; kt < PIN/16; ++kt) {
        {
            float4 v = *(const float4*)(Crow + kt*16 + aq*4);
            sA[(aq*4+0)*128 + ar] = v.x;
            sA[(aq*4+1)*128 + ar] = v.y;
            sA[(aq*4+2)*128 + ar] = v.z;
            sA[(aq*4+3)*128 + ar] = v.w;
        }
        {
            const float* wr = w1s + (size_t)bh * PIN + kt*16 + bq*8;
            float4 v0 = *(const float4*)(wr);
            float4 v1 = *(const float4*)(wr + 4);
            sB[(bq*8+0)*256 + bh] = v0.x;
            sB[(bq*8+1)*256 + bh] = v0.y;
            sB[(bq*8+2)*256 + bh] = v0.z;
            sB[(bq*8+3)*256 + bh] = v0.w;
            sB[(bq*8+4)*256 + bh] = v1.x;
            sB[(bq*8+5)*256 + bh] = v1.y;
            sB[(bq*8+6)*256 + bh] = v1.z;
            sB[(bq*8+7)*256 + bh] = v1.w;
        }
        __syncthreads();
        #pragma unroll
        for (int k = 0; k < 16; ++k) {
            const float* aR = sA + k*128 + ty*8;
            const unsigned long long* bR =
                (const unsigned long long*)(sB + k*256 + tx*8);
            unsigned long long bp0 = bR[0], bp1 = bR[1], bp2 = bR[2], bp3 = bR[3];
            #pragma unroll
            for (int i = 0; i < 8; ++i) {
                unsigned long long ap = splat2(aR[i]);
                ffma2(acc[i][0], ap, bp0);
                ffma2(acc[i][1], ap, bp1);
                ffma2(acc[i][2], ap, bp2);
                ffma2(acc[i][3], ap, bp3);
            }
        }
        __syncthreads();
    }

    // bias + relu -> sH; reset accumulators for layer 2
    {
        const float* b1 = pb1 + (size_t)s*HHD + tx*8;
        float bv[8];
        #pragma unroll
        for (int j = 0; j < 8; j++) bv[j] = b1[j];
        #pragma unroll
        for (int i = 0; i < 8; ++i) {
            float* dst = sH + (8*ty+i)*258 + tx*8;
            #pragma unroll
            for (int j2 = 0; j2 < 4; ++j2) {
                float2 v = unpack2(acc[i][j2]);
                dst[2*j2]   = fmaxf(v.x + bv[2*j2],   0.f);
                dst[2*j2+1] = fmaxf(v.y + bv[2*j2+1], 0.f);
                acc[i][j2] = 0ull;
            }
        }
    }
    __syncthreads();

    // ---- Layer 2: acc = H1 @ W2s^T  (H2 folded with w3 in epilogue) ----
    const float* w2s = pw2 + (size_t)s * (HHD * HHD);
    for (int kt = 0; kt < HHD/16; ++kt) {
        {
            const float* wr = w2s + (size_t)bh * HHD + kt*16 + bq*8;
            float4 v0 = *(const float4*)(wr);
            float4 v1 = *(const float4*)(wr + 4);
            sB[(bq*8+0)*256 + bh] = v0.x;
            sB[(bq*8+1)*256 + bh] = v0.y;
            sB[(bq*8+2)*256 + bh] = v0.z;
            sB[(bq*8+3)*256 + bh] = v0.w;
            sB[(bq*8+4)*256 + bh] = v1.x;
            sB[(bq*8+5)*256 + bh] = v1.y;
            sB[(bq*8+6)*256 + bh] = v1.z;
            sB[(bq*8+7)*256 + bh] = v1.w;
        }
        __syncthreads();
        #pragma unroll
        for (int k = 0; k < 16; ++k) {
            const float* aR = sH + (8*ty)*258 + kt*16 + k;
            const unsigned long long* bR =
                (const unsigned long long*)(sB + k*256 + tx*8);
            unsigned long long bp0 = bR[0], bp1 = bR[1], bp2 = bR[2], bp3 = bR[3];
            #pragma unroll
            for (int i = 0; i < 8; ++i) {
                unsigned long long ap = splat2(aR[i*258]);
                ffma2(acc[i][0], ap, bp0);
                ffma2(acc[i][1], ap, bp1);
                ffma2(acc[i][2], ap, bp2);
                ffma2(acc[i][3], ap, bp3);
            }
        }
        __syncthreads();
    }

    // ---- epilogue: sub[r] = sum_o relu(acc + b2[o]) * w3[o] + b3 ----
    {
        const float* b2 = pb2 + (size_t)s*HHD + tx*8;
        const float* w3 = pw3 + (size_t)s*HHD + tx*8;
        float bv[8], wv[8];
        #pragma unroll
        for (int j = 0; j < 8; j++) { bv[j] = b2[j]; wv[j] = w3[j]; }
        #pragma unroll
        for (int i = 0; i < 8; ++i) {
            float p = 0.f;
            #pragma unroll
            for (int j2 = 0; j2 < 4; ++j2) {
                float2 v = unpack2(acc[i][j2]);
                p += fmaxf(v.x + bv[2*j2],   0.f) * wv[2*j2];
                p += fmaxf(v.y + bv[2*j2+1], 0.f) * wv[2*j2+1];
            }
            sR[(8*ty+i)*33 + tx] = p;
        }
    }
    __syncthreads();
    if (t < 128) {
        float ssum = 0.f;
        #pragma unroll
        for (int c = 0; c < 32; ++c) ssum += sR[t*33 + c];
        out_sub[(size_t)(b0 + t)*SSC + s] = ssum + pb3[s];
    }
}

// ---------------- mimo: out[b,o] = sub[b,:] . mimo_w[o,:] + mimo_b[o] ----------------
__global__ void __launch_bounds__(256) mimo_kernel(
    const float* __restrict__ sub, const float* __restrict__ mw,
    const float* __restrict__ mb, float* __restrict__ out)
{
    int b = blockIdx.x;
    __shared__ float srow[SSC];
    int t = threadIdx.x;
    for (int i = t; i < SSC; i += 256) srow[i] = sub[(size_t)b*SSC + i];
    __syncthreads();
    int w = t >> 5, lane = t & 31;   // 8 warps = 8 outputs
    float sum = 0.f;
    for (int i = lane; i < SSC; i += 32) sum += srow[i] * mw[(size_t)w*SSC + i];
    #pragma unroll
    for (int off = 16; off; off >>= 1) sum += __shfl_xor_sync(0xffffffffu, sum, off);
    if (lane == 0) out[b*8 + w] = sum + mb[w];
}

// ---------------- launch ----------------
extern "C" void kernel_launch(void* const* d_in, const int* in_sizes, int n_in,
                              void* d_out, int out_size) {
    const float* positions = (const float*)d_in[0];
    const float* ue        = (const float*)d_in[1];
    const float* bsa       = (const float*)d_in[2];
    const float* extra     = (const float*)d_in[3];
    const float* att_w0    = (const float*)d_in[4];
    const float* att_b0    = (const float*)d_in[5];
    const float* att_wr    = (const float*)d_in[6];
    const float* att_br    = (const float*)d_in[7];
    const float* rad_w0    = (const float*)d_in[8];
    const float* rad_b0    = (const float*)d_in[9];
    const float* rad_wr    = (const float*)d_in[10];
    const float* rad_br    = (const float*)d_in[11];
    const float* p_w1      = (const float*)d_in[12];
    const float* p_b1      = (const float*)d_in[13];
    const float* p_w2      = (const float*)d_in[14];
    const float* p_b2      = (const float*)d_in[15];
    const float* p_w3      = (const float*)d_in[16];
    const float* p_b3      = (const float*)d_in[17];
    const float* mimo_w    = (const float*)d_in[18];
    const float* mimo_b    = (const float*)d_in[19];
    float* out = (float*)d_out;

    float *px, *ph0, *ph1, *pc;
    cudaGetSymbolAddress((void**)&px,  g_x);
    cudaGetSymbolAddress((void**)&ph0, g_h0);
    cudaGetSymbolAddress((void**)&ph1, g_h1);
    cudaGetSymbolAddress((void**)&pc,  g_c);
    float* h0n[2] = { ph0, ph0 + BB*HHD };
    float* h1n[2] = { ph1, ph1 + BB*HHD };

    concat_kernel<<<1, 512>>>(positions, ue, bsa, extra);

    dim3 mgrid(8, 4, 2);

    { // layer 0: K=19
        MlpArgs a;
        a.A0 = px; a.A1 = px; a.lda = INDIM; a.K = INDIM;
        a.W0 = att_w0; a.W1 = rad_w0; a.bi0 = att_b0; a.bi1 = rad_b0;
        a.out0 = h0n[0]; a.out1 = h0n[1]; a.ostride = HHD;
        a.o20 = nullptr; a.o21 = nullptr; a.o2stride = 0;
        mlp_gemm_relu<<<mgrid, 256>>>(a);
    }
    for (int l = 1; l <= 7; ++l) {
        MlpArgs a;
        float** inb  = (l & 1) ? h0n : h1n;
        float** outb = (l & 1) ? h1n : h0n;
        a.A0 = inb[0]; a.A1 = inb[1]; a.lda = HHD; a.K = HHD;
        a.W0 = att_wr + (size_t)(l-1)*HHD*HHD;
        a.W1 = rad_wr + (size_t)(l-1)*HHD*HHD;
        a.bi0 = att_br + (size_t)(l-1)*HHD;
        a.bi1 = rad_br + (size_t)(l-1)*HHD;
        if (l < 7) {
            a.out0 = outb[0]; a.out1 = outb[1]; a.ostride = HHD;
            a.o20 = nullptr; a.o21 = nullptr; a.o2stride = 0;
        } else {
            a.out0 = pc; a.out1 = pc + HHD; a.ostride = 2*HHD;
            a.o20 = out + ATT_OFF; a.o21 = out + RAD_OFF; a.o2stride = HHD;
        }
        mlp_gemm_relu<<<mgrid, 256>>>(a);
    }

    // prism (dominant): 173.6 KB dynamic smem, opt-in every call (idempotent)
    int smem_bytes = (16*128 + 16*256 + 128*258 + 128*33) * (int)sizeof(float);
    cudaFuncSetAttribute(prism_kernel,
                         cudaFuncAttributeMaxDynamicSharedMemorySize, smem_bytes);
    prism_kernel<<<dim3(4, 1024), 512, smem_bytes>>>(
        p_w1, p_b1, p_w2, p_b2, p_w3, p_b3, out /* sub at offset 0 */);

    mimo_kernel<<<512, 256>>>(out, mimo_w, mimo_b, out + MIMO_OFF);
}

// round 7
// speedup vs baseline: 1.0035x; 1.0035x over previous
#include <cuda_runtime.h>
#include <cstddef>

#define BB   512
#define SSC  1024
#define HHD  256
#define PIN  512
#define INDIM 19

#define MIMO_OFF (BB*SSC)              /* 524288 */
#define ATT_OFF  (MIMO_OFF + BB*8)     /* 528384 */
#define RAD_OFF  (ATT_OFF + BB*HHD)    /* 659456 */

// ---------------- device scratch (no allocations allowed) ----------------
__device__ __align__(256) float g_x[BB*INDIM];
__device__ __align__(256) float g_h0[2][BB*HHD];
__device__ __align__(256) float g_h1[2][BB*HHD];
__device__ __align__(256) float g_c[BB*2*HHD];

// ---------------- packed f32x2 helpers (Blackwell FFMA2) ----------------
__device__ __forceinline__ unsigned long long splat2(float a) {
    unsigned long long r;
    asm("mov.b64 %0, {%1, %1};" : "=l"(r) : "f"(a));
    return r;
}
__device__ __forceinline__ void ffma2(unsigned long long& d,
                                      unsigned long long a,
                                      unsigned long long b) {
    asm("fma.rn.f32x2 %0, %1, %2, %3;" : "=l"(d) : "l"(a), "l"(b), "l"(d));
}
__device__ __forceinline__ float2 unpack2(unsigned long long v) {
    float2 r;
    asm("mov.b64 {%0, %1}, %2;" : "=f"(r.x), "=f"(r.y) : "l"(v));
    return r;
}

// ---------------- concat x = [pos | ue | bs | extra] ----------------
__global__ void concat_kernel(const float* __restrict__ pos,
                              const float* __restrict__ ue,
                              const float* __restrict__ bsa,
                              const float* __restrict__ extra) {
    int b = threadIdx.x;
    if (b >= BB) return;
    float* x = g_x + b * INDIM;
    x[0] = pos[b*3+0]; x[1] = pos[b*3+1]; x[2] = pos[b*3+2];
    x[3] = ue[b*2+0];  x[4] = ue[b*2+1];
    x[5] = bsa[b*4+0]; x[6] = bsa[b*4+1]; x[7] = bsa[b*4+2]; x[8] = bsa[b*4+3];
    #pragma unroll
    for (int i = 0; i < 10; i++) x[9+i] = extra[b*10+i];
}

// ---------------- generic MLP layer: out = relu(A @ W^T + bias), both nets via blockIdx.z
struct MlpArgs {
    const float* A0; const float* A1;
    const float* W0; const float* W1;
    const float* bi0; const float* bi1;
    float* out0; float* out1;
    float* o20; float* o21;
    int lda, K, ostride, o2stride;
};

__global__ void __launch_bounds__(256) mlp_gemm_relu(MlpArgs p) {
    __shared__ __align__(16) float sA[16*66];
    __shared__ __align__(16) float sB[16*66];

    int net = blockIdx.z;
    const float* A    = net ? p.A1  : p.A0;
    const float* W    = net ? p.W1  : p.W0;
    const float* bias = net ? p.bi1 : p.bi0;
    float* out  = net ? p.out1 : p.out0;
    float* out2 = net ? p.o21  : p.o20;

    int b0 = blockIdx.x * 64, h0 = blockIdx.y * 64;
    int t  = threadIdx.x;
    int tx = t & 15, ty = t >> 4;     // 16 x 16 threads, 4x4 micro-tile
    int lr = t >> 2, lq = t & 3;      // load mapping: row 0..63, quarter 0..3

    unsigned long long acc[4][2];
    #pragma unroll
    for (int i = 0; i < 4; i++) { acc[i][0] = 0ull; acc[i][1] = 0ull; }

    int nkt = (p.K + 15) >> 4;
    for (int kt = 0; kt < nkt; ++kt) {
        int kbase = kt * 16;
        #pragma unroll
        for (int e = 0; e < 4; ++e) {
            int k = kbase + lq*4 + e;
            sA[(lq*4+e)*66 + lr] = (k < p.K) ? A[(size_t)(b0+lr)*p.lda + k] : 0.f;
            sB[(lq*4+e)*66 + lr] = (k < p.K) ? W[(size_t)(h0+lr)*p.K  + k] : 0.f;
        }
        __syncthreads();
        #pragma unroll
        for (int k = 0; k < 16; ++k) {
            unsigned long long bp0 = *(const unsigned long long*)&sB[k*66 + tx*4];
            unsigned long long bp1 = *(const unsigned long long*)&sB[k*66 + tx*4 + 2];
            #pragma unroll
            for (int i = 0; i < 4; ++i) {
                unsigned long long ap = splat2(sA[k*66 + ty*4 + i]);
                ffma2(acc[i][0], ap, bp0);
                ffma2(acc[i][1], ap, bp1);
            }
        }
        __syncthreads();
    }

    float bv[4];
    #pragma unroll
    for (int j = 0; j < 4; j++) bv[j] = bias[h0 + tx*4 + j];

    #pragma unroll
    for (int i = 0; i < 4; ++i) {
        int r = b0 + ty*4 + i;
        float2 v0 = unpack2(acc[i][0]);
        float2 v1 = unpack2(acc[i][1]);
        float o0 = fmaxf(v0.x + bv[0], 0.f);
        float o1 = fmaxf(v0.y + bv[1], 0.f);
        float o2 = fmaxf(v1.x + bv[2], 0.f);
        float o3 = fmaxf(v1.y + bv[3], 0.f);
        float* po = out + (size_t)r * p.ostride + h0 + tx*4;
        po[0] = o0; po[1] = o1; po[2] = o2; po[3] = o3;
        if (out2) {
            float* q = out2 + (size_t)r * p.o2stride + h0 + tx*4;
            q[0] = o0; q[1] = o1; q[2] = o2; q[3] = o3;
        }
    }
}

// ---------------- prism: per-subcarrier fused 3-layer MLP ----------------
// grid = (4 B-chunks, 1024 subcarriers), 512 threads, 1 CTA/SM (smem 173.6 KB)
__global__ void __launch_bounds__(512, 1) prism_kernel(
    const float* __restrict__ pw1, const float* __restrict__ pb1,
    const float* __restrict__ pw2, const float* __restrict__ pb2,
    const float* __restrict__ pw3, const float* __restrict__ pb3,
    float* __restrict__ out_sub)
{
    extern __shared__ float sm[];
    float* sA = sm;                         // [16][128]  C k-tiles (k-major)
    float* sB = sm + 16*128;                // [16][256]  W k-tiles (k-major)
    float* sH = sB + 16*256;                // [128][258] H1 (row-major, padded)
    float* sR = sH + 128*258;               // [128][33]  reduction scratch

    int s  = blockIdx.y;
    int b0 = blockIdx.x * 128;
    int t  = threadIdx.x;
    int tx = t & 31, ty = t >> 5;           // 32 x 16 threads, 8x8 micro-tile

    int ar = t & 127, aq = t >> 7;          // A-load: row, k-quarter (0..3)
    int bh = t & 255, bq = t >> 8;          // B-load: h,   k-half    (0..1)

    const float* w1s  = pw1 + (size_t)s * (HHD * PIN);
    const float* Crow = g_c + (size_t)(b0 + ar) * (2*HHD);

    unsigned long long acc[8][4];
    #pragma unroll
    for (int i = 0; i < 8; i++)
        #pragma unroll
        for (int j = 0; j < 4; j++) acc[i][j] = 0ull;

    // ---- Layer 1: H1[128,256] = relu(C[128,512] @ W1s^T + b1) ----
    for (int kt = 0; kt < PIN/16; ++kt) {
        {
            float4 v = *(const float4*)(Crow + kt*16 + aq*4);
            sA[(aq*4+0)*128 + ar] = v.x;
            sA[(aq*4+1)*128 + ar] = v.y;
            sA[(aq*4+2)*128 + ar] = v.z;
            sA[(aq*4+3)*128 + ar] = v.w;
        }
        {
            const float* wr = w1s + (size_t)bh * PIN + kt*16 + bq*8;
            float4 v0 = *(const float4*)(wr);
            float4 v1 = *(const float4*)(wr + 4);
            sB[(bq*8+0)*256 + bh] = v0.x;
            sB[(bq*8+1)*256 + bh] = v0.y;
            sB[(bq*8+2)*256 + bh] = v0.z;
            sB[(bq*8+3)*256 + bh] = v0.w;
            sB[(bq*8+4)*256 + bh] = v1.x;
            sB[(bq*8+5)*256 + bh] = v1.y;
            sB[(bq*8+6)*256 + bh] = v1.z;
            sB[(bq*8+7)*256 + bh] = v1.w;
        }
        __syncthreads();
        #pragma unroll
        for (int k = 0; k < 16; ++k) {
            const float* aR = sA + k*128 + ty*8;
            const unsigned long long* bR =
                (const unsigned long long*)(sB + k*256 + tx*8);
            unsigned long long bp0 = bR[0], bp1 = bR[1], bp2 = bR[2], bp3 = bR[3];
            #pragma unroll
            for (int i = 0; i < 8; ++i) {
                unsigned long long ap = splat2(aR[i]);
                ffma2(acc[i][0], ap, bp0);
                ffma2(acc[i][1], ap, bp1);
                ffma2(acc[i][2], ap, bp2);
                ffma2(acc[i][3], ap, bp3);
            }
        }
        __syncthreads();
    }

    // bias + relu -> sH; reset accumulators for layer 2
    {
        const float* b1 = pb1 + (size_t)s*HHD + tx*8;
        float bv[8];
        #pragma unroll
        for (int j = 0; j < 8; j++) bv[j] = b1[j];
        #pragma unroll
        for (int i = 0; i < 8; ++i) {
            float* dst = sH + (8*ty+i)*258 + tx*8;
            #pragma unroll
            for (int j2 = 0; j2 < 4; ++j2) {
                float2 v = unpack2(acc[i][j2]);
                dst[2*j2]   = fmaxf(v.x + bv[2*j2],   0.f);
                dst[2*j2+1] = fmaxf(v.y + bv[2*j2+1], 0.f);
                acc[i][j2] = 0ull;
            }
        }
    }
    __syncthreads();

    // ---- Layer 2: acc = H1 @ W2s^T  (H2 folded with w3 in epilogue) ----
    const float* w2s = pw2 + (size_t)s * (HHD * HHD);
    for (int kt = 0; kt < HHD/16; ++kt) {
        {
            const float* wr = w2s + (size_t)bh * HHD + kt*16 + bq*8;
            float4 v0 = *(const float4*)(wr);
            float4 v1 = *(const float4*)(wr + 4);
            sB[(bq*8+0)*256 + bh] = v0.x;
            sB[(bq*8+1)*256 + bh] = v0.y;
            sB[(bq*8+2)*256 + bh] = v0.z;
            sB[(bq*8+3)*256 + bh] = v0.w;
            sB[(bq*8+4)*256 + bh] = v1.x;
            sB[(bq*8+5)*256 + bh] = v1.y;
            sB[(bq*8+6)*256 + bh] = v1.z;
            sB[(bq*8+7)*256 + bh] = v1.w;
        }
        __syncthreads();
        #pragma unroll
        for (int k = 0; k < 16; ++k) {
            const float* aR = sH + (8*ty)*258 + kt*16 + k;
            const unsigned long long* bR =
                (const unsigned long long*)(sB + k*256 + tx*8);
            unsigned long long bp0 = bR[0], bp1 = bR[1], bp2 = bR[2], bp3 = bR[3];
            #pragma unroll
            for (int i = 0; i < 8; ++i) {
                unsigned long long ap = splat2(aR[i*258]);
                ffma2(acc[i][0], ap, bp0);
                ffma2(acc[i][1], ap, bp1);
                ffma2(acc[i][2], ap, bp2);
                ffma2(acc[i][3], ap, bp3);
            }
        }
        __syncthreads();
    }

    // ---- epilogue: sub[r] = sum_o relu(acc + b2[o]) * w3[o] + b3 ----
    {
        const float* b2 = pb2 + (size_t)s*HHD + tx*8;
        const float* w3 = pw3 + (size_t)s*HHD + tx*8;
        float bv[8], wv[8];
        #pragma unroll
        for (int j = 0; j < 8; j++) { bv[j] = b2[j]; wv[j] = w3[j]; }
        #pragma unroll
        for (int i = 0; i < 8; ++i) {
            float p = 0.f;
            #pragma unroll
            for (int j2 = 0; j2 < 4; ++j2) {
                float2 v = unpack2(acc[i][j2]);
                p += fmaxf(v.x + bv[2*j2],   0.f) * wv[2*j2];
                p += fmaxf(v.y + bv[2*j2+1], 0.f) * wv[2*j2+1];
            }
            sR[(8*ty+i)*33 + tx] = p;
        }
    }
    __syncthreads();
    if (t < 128) {
        float ssum = 0.f;
        #pragma unroll
        for (int c = 0; c < 32; ++c) ssum += sR[t*33 + c];
        out_sub[(size_t)(b0 + t)*SSC + s] = ssum + pb3[s];
    }
}

// ---------------- mimo: out[b,o] = sub[b,:] . mimo_w[o,:] + mimo_b[o] ----------------
__global__ void __launch_bounds__(256) mimo_kernel(
    const float* __restrict__ sub, const float* __restrict__ mw,
    const float* __restrict__ mb, float* __restrict__ out)
{
    int b = blockIdx.x;
    __shared__ float srow[SSC];
    int t = threadIdx.x;
    for (int i = t; i < SSC; i += 256) srow[i] = sub[(size_t)b*SSC + i];
    __syncthreads();
    int w = t >> 5, lane = t & 31;   // 8 warps = 8 outputs
    float sum = 0.f;
    for (int i = lane; i < SSC; i += 32) sum += srow[i] * mw[(size_t)w*SSC + i];
    #pragma unroll
    for (int off = 16; off; off >>= 1) sum += __shfl_xor_sync(0xffffffffu, sum, off);
    if (lane == 0) out[b*8 + w] = sum + mb[w];
}

// ---------------- launch ----------------
extern "C" void kernel_launch(void* const* d_in, const int* in_sizes, int n_in,
                              void* d_out, int out_size) {
    const float* positions = (const float*)d_in[0];
    const float* ue        = (const float*)d_in[1];
    const float* bsa       = (const float*)d_in[2];
    const float* extra     = (const float*)d_in[3];
    const float* att_w0    = (const float*)d_in[4];
    const float* att_b0    = (const float*)d_in[5];
    const float* att_wr    = (const float*)d_in[6];
    const float* att_br    = (const float*)d_in[7];
    const float* rad_w0    = (const float*)d_in[8];
    const float* rad_b0    = (const float*)d_in[9];
    const float* rad_wr    = (const float*)d_in[10];
    const float* rad_br    = (const float*)d_in[11];
    const float* p_w1      = (const float*)d_in[12];
    const float* p_b1      = (const float*)d_in[13];
    const float* p_w2      = (const float*)d_in[14];
    const float* p_b2      = (const float*)d_in[15];
    const float* p_w3      = (const float*)d_in[16];
    const float* p_b3      = (const float*)d_in[17];
    const float* mimo_w    = (const float*)d_in[18];
    const float* mimo_b    = (const float*)d_in[19];
    float* out = (float*)d_out;

    float *px, *ph0, *ph1, *pc;
    cudaGetSymbolAddress((void**)&px,  g_x);
    cudaGetSymbolAddress((void**)&ph0, g_h0);
    cudaGetSymbolAddress((void**)&ph1, g_h1);
    cudaGetSymbolAddress((void**)&pc,  g_c);
    float* h0n[2] = { ph0, ph0 + BB*HHD };
    float* h1n[2] = { ph1, ph1 + BB*HHD };

    concat_kernel<<<1, 512>>>(positions, ue, bsa, extra);

    dim3 mgrid(8, 4, 2);

    { // layer 0: K=19
        MlpArgs a;
        a.A0 = px; a.A1 = px; a.lda = INDIM; a.K = INDIM;
        a.W0 = att_w0; a.W1 = rad_w0; a.bi0 = att_b0; a.bi1 = rad_b0;
        a.out0 = h0n[0]; a.out1 = h0n[1]; a.ostride = HHD;
        a.o20 = nullptr; a.o21 = nullptr; a.o2stride = 0;
        mlp_gemm_relu<<<mgrid, 256>>>(a);
    }
    for (int l = 1; l <= 7; ++l) {
        MlpArgs a;
        float** inb  = (l & 1) ? h0n : h1n;
        float** outb = (l & 1) ? h1n : h0n;
        a.A0 = inb[0]; a.A1 = inb[1]; a.lda = HHD; a.K = HHD;
        a.W0 = att_wr + (size_t)(l-1)*HHD*HHD;
        a.W1 = rad_wr + (size_t)(l-1)*HHD*HHD;
        a.bi0 = att_br + (size_t)(l-1)*HHD;
        a.bi1 = rad_br + (size_t)(l-1)*HHD;
        if (l < 7) {
            a.out0 = outb[0]; a.out1 = outb[1]; a.ostride = HHD;
            a.o20 = nullptr; a.o21 = nullptr; a.o2stride = 0;
        } else {
            a.out0 = pc; a.out1 = pc + HHD; a.ostride = 2*HHD;
            a.o20 = out + ATT_OFF; a.o21 = out + RAD_OFF; a.o2stride = HHD;
        }
        mlp_gemm_relu<<<mgrid, 256>>>(a);
    }

    // prism (dominant): 173.6 KB dynamic smem, opt-in every call (idempotent)
    int smem_bytes = (16*128 + 16*256 + 128*258 + 128*33) * (int)sizeof(float);
    cudaFuncSetAttribute(prism_kernel,
                         cudaFuncAttributeMaxDynamicSharedMemorySize, smem_bytes);
    prism_kernel<<<dim3(4, 1024), 512, smem_bytes>>>(
        p_w1, p_b1, p_w2, p_b2, p_w3, p_b3, out /* sub at offset 0 */);

    mimo_kernel<<<512, 256>>>(out, mimo_w, mimo_b, out + MIMO_OFF);
}